// round 12
// baseline (speedup 1.0000x reference)
#include <cuda_runtime.h>
#include <stdint.h>

// SkipGramNS: out[i] = dot(cxt_weight[ctx_idx[i]], tgt_weight[tgt_idx[i]])
// N=1e6, D=128, V=1e5.
//
// Model (R3..R11): binder is the L1tex gather-wavefront queue (~2cyc/wf,
// hit/miss-independent). Direct kernel needs 8 wf/pair -> ~70us floor.
// R12 pipeline: bucket pairs by context row (32 rows/bucket); dot stages the
// bucket's C rows in SMEM via cp.async.bulk (TMA path, no L1tex wavefronts),
// T gathered via 4x LDG.128 (4 wf/pair), C via conflict-free LDS.128.
//   K1 scatter: 4 pairs/thread (int4), independent atomic chains
//   K2 dot: one CTA per bucket
//   K3 overflow sweep (normally empty)

#define D_SHIFT  7            // D = 128
#define B_SHIFT  5            // 32 rows per bucket
#define ROWS_PB  32
#define BMAX     4096         // supports V <= 131072
#define SLOTS    512          // Poisson(mean 320) -> P(overflow) ~ 0
#define NMAX_    (1 << 20)    // supports n <= 1,048,576

__device__ int                g_cursor[BMAX];
__device__ int                g_ovcnt;
__device__ unsigned long long g_scratch[BMAX * SLOTS];   // 16MB
__device__ unsigned long long g_ovf[NMAX_];              // 8MB

__device__ __forceinline__ unsigned long long pack_pair(int c, int t, int i) {
    return (unsigned long long)i |
           ((unsigned long long)t << 20) |
           ((unsigned long long)c << 40);
}

__device__ __forceinline__ void scatter_one(int c, int t, int i) {
    const int b = c >> B_SHIFT;
    const int s = atomicAdd(&g_cursor[b], 1);
    const unsigned long long v = pack_pair(c, t, i);
    if (s < SLOTS) g_scratch[(size_t)b * SLOTS + s] = v;
    else           g_ovf[atomicAdd(&g_ovcnt, 1)] = v;
}

// ---------- K1: scatter, 4 pairs per thread ----------
__global__ void __launch_bounds__(256)
scatter_kernel(const int* __restrict__ ci, const int* __restrict__ ti, int n)
{
    const int i4 = (blockIdx.x * blockDim.x + threadIdx.x) * 4;
    if (i4 >= n) return;

    if (i4 + 3 < n) {
        const int4 c = __ldg(reinterpret_cast<const int4*>(ci + i4));
        const int4 t = __ldg(reinterpret_cast<const int4*>(ti + i4));
        scatter_one(c.x, t.x, i4);
        scatter_one(c.y, t.y, i4 + 1);
        scatter_one(c.z, t.z, i4 + 2);
        scatter_one(c.w, t.w, i4 + 3);
    } else {
        for (int i = i4; i < n; i++)
            scatter_one(__ldg(&ci[i]), __ldg(&ti[i]), i);
    }
}

// ---------- K2: dot, one CTA per bucket, C staged in SMEM via TMA bulk ----------
__global__ void __launch_bounds__(256)
dot_kernel(const float* __restrict__ cxt_w,
           const float* __restrict__ tgt_w,
           float* __restrict__ out, int V)
{
    __shared__ __align__(16) float cs[ROWS_PB * 128];   // 16KB
    __shared__ __align__(8)  unsigned long long mbar;

    const int b   = blockIdx.x;
    const int cnt = min(__ldg(&g_cursor[b]), SLOTS);
    if (cnt == 0) return;                                // uniform

    const unsigned long long* __restrict__ bucket =
        g_scratch + (size_t)b * SLOTS;

    // stage this bucket's C rows via cp.async.bulk (bypasses L1tex)
    const int r0    = b << B_SHIFT;
    const int nrows = min(ROWS_PB, V - r0);
    const unsigned bytes = (unsigned)nrows * 512u;

    uint32_t mbar_addr, cs_addr;
    {
        uint64_t tmp;
        asm("cvta.to.shared.u64 %0, %1;" : "=l"(tmp) : "l"(&mbar));
        mbar_addr = (uint32_t)tmp;
        asm("cvta.to.shared.u64 %0, %1;" : "=l"(tmp) : "l"(cs));
        cs_addr = (uint32_t)tmp;
    }

    if (threadIdx.x == 0) {
        asm volatile("mbarrier.init.shared.b64 [%0], %1;"
                     :: "r"(mbar_addr), "r"(1u) : "memory");
        asm volatile("mbarrier.arrive.expect_tx.shared.b64 _, [%0], %1;"
                     :: "r"(mbar_addr), "r"(bytes) : "memory");
        const float* src = cxt_w + ((size_t)r0 << D_SHIFT);
        asm volatile("cp.async.bulk.shared::cta.global.mbarrier::complete_tx::bytes"
                     " [%0], [%1], %2, [%3];"
                     :: "r"(cs_addr), "l"(src), "r"(bytes), "r"(mbar_addr)
                     : "memory");
    }
    __syncthreads();

    // wait for the bulk copy
    {
        uint32_t done;
        asm volatile(
            "{\n\t.reg .pred p;\n\t"
            "mbarrier.try_wait.parity.acquire.cta.shared::cta.b64 p, [%1], 0;\n\t"
            "selp.b32 %0, 1, 0, p;\n\t}"
            : "=r"(done) : "r"(mbar_addr) : "memory");
        if (!done) {
            asm volatile(
                "{\n\t.reg .pred P1;\n\t"
                "WL_%=:\n\t"
                "mbarrier.try_wait.parity.acquire.cta.shared::cta.b64 P1, [%0], 0, 0x989680;\n\t"
                "@P1 bra.uni WD_%=;\n\t"
                "bra.uni WL_%=;\n\t"
                "WD_%=:\n\t}"
                :: "r"(mbar_addr) : "memory");
        }
    }

    const int lane  = threadIdx.x & 31;
    const int warp  = threadIdx.x >> 5;   // 0..7
    const int group = lane >> 3;          // 0..3
    const int j     = lane & 7;           // 0..7

    for (int base = warp * 4; base < cnt; base += 32) {
        const int p   = base + group;
        const bool ok = (p < cnt);
        const unsigned long long v = __ldg(&bucket[ok ? p : 0]);

        const int idx = (int)(v & 0xFFFFFu);
        const int ti  = (int)((v >> 20) & 0xFFFFFu);
        const int cl  = (int)(v >> 40) & (ROWS_PB - 1);

        const float4* __restrict__ tv =
            reinterpret_cast<const float4*>(tgt_w + ((size_t)ti << D_SHIFT));
        const float4* __restrict__ cv =
            reinterpret_cast<const float4*>(cs + cl * 128);

        // T: 4 LDG.128, each one full 128B line (4 L1tex wavefronts/pair)
        const float4 b0 = __ldg(&tv[j]);
        const float4 b1 = __ldg(&tv[j +  8]);
        const float4 b2 = __ldg(&tv[j + 16]);
        const float4 b3 = __ldg(&tv[j + 24]);
        // C: SMEM crossbar (conflict-free: 8 lanes x float4 = all 32 banks)
        const float4 a0 = cv[j];
        const float4 a1 = cv[j +  8];
        const float4 a2 = cv[j + 16];
        const float4 a3 = cv[j + 24];

        float s0 = 0.f, s1 = 0.f, s2 = 0.f, s3 = 0.f;
        s0 = fmaf(a0.x, b0.x, s0); s0 = fmaf(a0.y, b0.y, s0);
        s0 = fmaf(a0.z, b0.z, s0); s0 = fmaf(a0.w, b0.w, s0);
        s1 = fmaf(a1.x, b1.x, s1); s1 = fmaf(a1.y, b1.y, s1);
        s1 = fmaf(a1.z, b1.z, s1); s1 = fmaf(a1.w, b1.w, s1);
        s2 = fmaf(a2.x, b2.x, s2); s2 = fmaf(a2.y, b2.y, s2);
        s2 = fmaf(a2.z, b2.z, s2); s2 = fmaf(a2.w, b2.w, s2);
        s3 = fmaf(a3.x, b3.x, s3); s3 = fmaf(a3.y, b3.y, s3);
        s3 = fmaf(a3.z, b3.z, s3); s3 = fmaf(a3.w, b3.w, s3);
        float sv = (s0 + s1) + (s2 + s3);

        sv += __shfl_xor_sync(0xFFFFFFFFu, sv, 4);
        sv += __shfl_xor_sync(0xFFFFFFFFu, sv, 2);
        sv += __shfl_xor_sync(0xFFFFFFFFu, sv, 1);

        if (ok && j == 0)
            __stcs(&out[idx], sv);
    }
}

// ---------- K3: overflow sweep (normally 0 pairs) ----------
__global__ void __launch_bounds__(256)
ovf_kernel(const float* __restrict__ cxt_w,
           const float* __restrict__ tgt_w,
           float* __restrict__ out)
{
    const int m = g_ovcnt;
    if (m == 0) return;

    const int lane  = threadIdx.x & 31;
    const int group = lane >> 3;
    const int j     = lane & 7;
    const int warp_g = (blockIdx.x * blockDim.x + threadIdx.x) >> 5;
    const int nwarps = (gridDim.x * blockDim.x) >> 5;

    for (int base = warp_g * 4; base < m; base += nwarps * 4) {
        const int p   = base + group;
        const bool ok = (p < m);
        const unsigned long long v = g_ovf[ok ? p : 0];

        const int idx = (int)(v & 0xFFFFFu);
        const int ti  = (int)((v >> 20) & 0xFFFFFu);
        const int ci  = (int)(v >> 40);

        const float4* __restrict__ tv =
            reinterpret_cast<const float4*>(tgt_w + ((size_t)ti << D_SHIFT));
        const float4* __restrict__ cv =
            reinterpret_cast<const float4*>(cxt_w + ((size_t)ci << D_SHIFT));

        float sv = 0.f;
        #pragma unroll
        for (int k = 0; k < 4; k++) {
            const float4 a = __ldg(&cv[j + 8 * k]);
            const float4 b = __ldg(&tv[j + 8 * k]);
            sv = fmaf(a.x, b.x, sv); sv = fmaf(a.y, b.y, sv);
            sv = fmaf(a.z, b.z, sv); sv = fmaf(a.w, b.w, sv);
        }
        sv += __shfl_xor_sync(0xFFFFFFFFu, sv, 4);
        sv += __shfl_xor_sync(0xFFFFFFFFu, sv, 2);
        sv += __shfl_xor_sync(0xFFFFFFFFu, sv, 1);

        if (ok && j == 0)
            __stcs(&out[idx], sv);
    }
}

// ---------- fallback: proven direct kernel (R3 geometry, ~70us) ----------
__global__ void __launch_bounds__(256)
direct_kernel(const int* __restrict__ ctx_idx,
              const int* __restrict__ tgt_idx,
              const float* __restrict__ cxt_w,
              const float* __restrict__ tgt_w,
              float* __restrict__ out, int n)
{
    const int warp_id = (blockIdx.x * blockDim.x + threadIdx.x) >> 5;
    const int lane    = threadIdx.x & 31;
    const int group   = lane >> 3;
    const int j       = lane & 7;
    const int pair    = warp_id * 4 + group;
    if (pair >= n) return;

    const long long c = (long long)__ldg(&ctx_idx[pair]);
    const long long t = (long long)__ldg(&tgt_idx[pair]);
    const float4* __restrict__ cv = reinterpret_cast<const float4*>(cxt_w + c * 128);
    const float4* __restrict__ tv = reinterpret_cast<const float4*>(tgt_w + t * 128);

    float s = 0.f;
    #pragma unroll
    for (int k = 0; k < 4; k++) {
        const float4 a = __ldg(&cv[j + 8 * k]);
        const float4 b = __ldg(&tv[j + 8 * k]);
        s = fmaf(a.x, b.x, s); s = fmaf(a.y, b.y, s);
        s = fmaf(a.z, b.z, s); s = fmaf(a.w, b.w, s);
    }
    s += __shfl_xor_sync(0xFFFFFFFFu, s, 4);
    s += __shfl_xor_sync(0xFFFFFFFFu, s, 2);
    s += __shfl_xor_sync(0xFFFFFFFFu, s, 1);

    if (j == 0)
        __stcs(&out[pair], s);
}

extern "C" void kernel_launch(void* const* d_in, const int* in_sizes, int n_in,
                              void* d_out, int out_size)
{
    const int*   ctx_idx = (const int*)d_in[0];
    const int*   tgt_idx = (const int*)d_in[1];
    const float* cxt_w   = (const float*)d_in[2];
    const float* tgt_w   = (const float*)d_in[3];
    float*       out     = (float*)d_out;

    const int n = in_sizes[0];                 // 1,000,000 pairs
    const int V = in_sizes[2] >> D_SHIFT;      // 100,000 rows

    const bool shapes_ok = (n > 0) && (n <= NMAX_) &&
                           ((in_sizes[2] & 127) == 0) &&
                           (V <= (BMAX << B_SHIFT)) && (V <= (1 << 20));

    if (shapes_ok) {
        void* cp = nullptr; void* op = nullptr;
        cudaGetSymbolAddress(&cp, g_cursor);
        cudaGetSymbolAddress(&op, g_ovcnt);
        cudaMemsetAsync(cp, 0, BMAX * sizeof(int));
        cudaMemsetAsync(op, 0, sizeof(int));

        const int sthreads = 256;
        const int spairs   = sthreads * 4;
        scatter_kernel<<<(n + spairs - 1) / spairs, sthreads>>>(ctx_idx, tgt_idx, n);

        const int NB = (V + ROWS_PB - 1) >> B_SHIFT;
        dot_kernel<<<NB, 256>>>(cxt_w, tgt_w, out, V);
        ovf_kernel<<<64, 256>>>(cxt_w, tgt_w, out);
    } else {
        const int threads = 256;
        const int pairs_per_block = (threads / 32) * 4;
        const int blocks = (n + pairs_per_block - 1) / pairs_per_block;
        direct_kernel<<<blocks, threads>>>(ctx_idx, tgt_idx, cxt_w, tgt_w, out, n);
    }
}

// round 13
// speedup vs baseline: 1.0964x; 1.0964x over previous
#include <cuda_runtime.h>
#include <stdint.h>

// SkipGramNS: out[i] = dot(cxt_weight[ctx_idx[i]], tgt_weight[tgt_idx[i]])
// N=1e6, D=128, V=1e5.
//
// Model: direct-LDG kernel floor = 8 L1tex line-touches/pair x ~2.07cyc ~ 70us
// (R3/R6/R10). Escape: bucket by context row; C rows via SMEM (LDS pipe),
// T via 4 single-line LDG.128 -> 4 wf/pair. Binder was scatter's atomics:
// R13 sub-partitions each bucket cursor 8x (contention 320 -> ~40/address)
// and issues the 4 atomics branchlessly before any dependent store.

#define D_SHIFT   7            // D = 128
#define B_SHIFT   5            // 32 rows per bucket
#define ROWS_PB   32
#define BMAX      4096         // supports V <= 131072
#define SUBS      8            // sub-cursors per bucket
#define SLOT_SUB  96           // slots per sub (Poisson(40) -> P(ovf) ~ 0)
#define NMAX_     (1 << 20)

__device__ int                g_cursor[BMAX * SUBS];
__device__ int                g_ovcnt;
__device__ unsigned long long g_scratch[BMAX * SUBS * SLOT_SUB];  // 25MB
__device__ unsigned long long g_ovf[NMAX_];                       // 8MB

__device__ __forceinline__ unsigned long long pack_pair(int c, int t, int i) {
    return (unsigned long long)i |
           ((unsigned long long)t << 20) |
           ((unsigned long long)c << 40);
}

// ---------- K1: scatter, 4 pairs/thread, branchless atomic batch ----------
__global__ void __launch_bounds__(256)
scatter_kernel(const int* __restrict__ ci, const int* __restrict__ ti, int n)
{
    const int gtid = blockIdx.x * blockDim.x + threadIdx.x;
    const int i4   = gtid * 4;
    if (i4 >= n) return;
    const int sub = gtid & (SUBS - 1);

    if (i4 + 3 < n) {
        const int4 c = __ldg(reinterpret_cast<const int4*>(ci + i4));
        const int4 t = __ldg(reinterpret_cast<const int4*>(ti + i4));

        const int k0 = (c.x >> B_SHIFT) * SUBS + sub;
        const int k1 = (c.y >> B_SHIFT) * SUBS + sub;
        const int k2 = (c.z >> B_SHIFT) * SUBS + sub;
        const int k3 = (c.w >> B_SHIFT) * SUBS + sub;

        // 4 independent atomics, no branches between them
        const int s0 = atomicAdd(&g_cursor[k0], 1);
        const int s1 = atomicAdd(&g_cursor[k1], 1);
        const int s2 = atomicAdd(&g_cursor[k2], 1);
        const int s3 = atomicAdd(&g_cursor[k3], 1);

        const unsigned long long v0 = pack_pair(c.x, t.x, i4);
        const unsigned long long v1 = pack_pair(c.y, t.y, i4 + 1);
        const unsigned long long v2 = pack_pair(c.z, t.z, i4 + 2);
        const unsigned long long v3 = pack_pair(c.w, t.w, i4 + 3);

        if (s0 < SLOT_SUB) g_scratch[(size_t)k0 * SLOT_SUB + s0] = v0;
        else               g_ovf[atomicAdd(&g_ovcnt, 1)] = v0;
        if (s1 < SLOT_SUB) g_scratch[(size_t)k1 * SLOT_SUB + s1] = v1;
        else               g_ovf[atomicAdd(&g_ovcnt, 1)] = v1;
        if (s2 < SLOT_SUB) g_scratch[(size_t)k2 * SLOT_SUB + s2] = v2;
        else               g_ovf[atomicAdd(&g_ovcnt, 1)] = v2;
        if (s3 < SLOT_SUB) g_scratch[(size_t)k3 * SLOT_SUB + s3] = v3;
        else               g_ovf[atomicAdd(&g_ovcnt, 1)] = v3;
    } else {
        for (int i = i4; i < n; i++) {
            const int c = __ldg(&ci[i]);
            const int t = __ldg(&ti[i]);
            const int k = (c >> B_SHIFT) * SUBS + sub;
            const int s = atomicAdd(&g_cursor[k], 1);
            const unsigned long long v = pack_pair(c, t, i);
            if (s < SLOT_SUB) g_scratch[(size_t)k * SLOT_SUB + s] = v;
            else              g_ovf[atomicAdd(&g_ovcnt, 1)] = v;
        }
    }
}

// ---------- K2: dot, one CTA per bucket, C rows staged in SMEM ----------
__global__ void __launch_bounds__(512)
dot_kernel(const float* __restrict__ cxt_w,
           const float* __restrict__ tgt_w,
           float* __restrict__ out, int V)
{
    __shared__ __align__(16) float cs[ROWS_PB * 128];   // 16KB
    __shared__ int scnt[SUBS];

    const int b = blockIdx.x;

    // stage this bucket's C rows (coalesced float4 -> SMEM)
    {
        const int r0    = b << B_SHIFT;
        const int nrows = min(ROWS_PB, V - r0);
        if (nrows > 0) {
            const float4* __restrict__ src =
                reinterpret_cast<const float4*>(cxt_w + ((size_t)r0 << D_SHIFT));
            float4* dst = reinterpret_cast<float4*>(cs);
            const int nv = nrows * 32;
            for (int k = threadIdx.x; k < nv; k += 512)
                dst[k] = __ldg(&src[k]);
        }
        if (threadIdx.x < SUBS)
            scnt[threadIdx.x] = min(__ldg(&g_cursor[b * SUBS + threadIdx.x]),
                                    SLOT_SUB);
    }
    __syncthreads();

    const int lane  = threadIdx.x & 31;
    const int warp  = threadIdx.x >> 5;   // 0..15
    const int sub   = warp >> 1;          // 0..7: segment owned by warp pair
    const int half  = warp & 1;           // 0/1 within the pair
    const int group = lane >> 3;          // 0..3
    const int j     = lane & 7;           // 0..7

    const int cnt = scnt[sub];
    const unsigned long long* __restrict__ seg =
        g_scratch + ((size_t)b * SUBS + sub) * SLOT_SUB;

    for (int base = half * 4; base < cnt; base += 8) {
        const int p   = base + group;
        const bool ok = (p < cnt);
        const unsigned long long v = __ldg(&seg[ok ? p : 0]);

        const int idx = (int)(v & 0xFFFFFu);
        const int ti  = (int)((v >> 20) & 0xFFFFFu);
        const int cl  = (int)(v >> 40) & (ROWS_PB - 1);

        const float4* __restrict__ tv =
            reinterpret_cast<const float4*>(tgt_w + ((size_t)ti << D_SHIFT));
        const float4* __restrict__ cv =
            reinterpret_cast<const float4*>(cs + cl * 128);

        // T: 4 LDG.128, each a full 128B line (4 L1tex wavefronts/pair)
        const float4 b0 = __ldg(&tv[j]);
        const float4 b1 = __ldg(&tv[j +  8]);
        const float4 b2 = __ldg(&tv[j + 16]);
        const float4 b3 = __ldg(&tv[j + 24]);
        // C: SMEM crossbar (conflict-free 8 lanes x float4)
        const float4 a0 = cv[j];
        const float4 a1 = cv[j +  8];
        const float4 a2 = cv[j + 16];
        const float4 a3 = cv[j + 24];

        float s0 = 0.f, s1 = 0.f, s2 = 0.f, s3 = 0.f;
        s0 = fmaf(a0.x, b0.x, s0); s0 = fmaf(a0.y, b0.y, s0);
        s0 = fmaf(a0.z, b0.z, s0); s0 = fmaf(a0.w, b0.w, s0);
        s1 = fmaf(a1.x, b1.x, s1); s1 = fmaf(a1.y, b1.y, s1);
        s1 = fmaf(a1.z, b1.z, s1); s1 = fmaf(a1.w, b1.w, s1);
        s2 = fmaf(a2.x, b2.x, s2); s2 = fmaf(a2.y, b2.y, s2);
        s2 = fmaf(a2.z, b2.z, s2); s2 = fmaf(a2.w, b2.w, s2);
        s3 = fmaf(a3.x, b3.x, s3); s3 = fmaf(a3.y, b3.y, s3);
        s3 = fmaf(a3.z, b3.z, s3); s3 = fmaf(a3.w, b3.w, s3);
        float sv = (s0 + s1) + (s2 + s3);

        sv += __shfl_xor_sync(0xFFFFFFFFu, sv, 4);
        sv += __shfl_xor_sync(0xFFFFFFFFu, sv, 2);
        sv += __shfl_xor_sync(0xFFFFFFFFu, sv, 1);

        if (ok && j == 0)
            __stcs(&out[idx], sv);
    }
}

// ---------- K3: overflow sweep (normally 0 pairs) ----------
__global__ void __launch_bounds__(256)
ovf_kernel(const float* __restrict__ cxt_w,
           const float* __restrict__ tgt_w,
           float* __restrict__ out)
{
    const int m = g_ovcnt;
    if (m == 0) return;

    const int lane   = threadIdx.x & 31;
    const int group  = lane >> 3;
    const int j      = lane & 7;
    const int warp_g = (blockIdx.x * blockDim.x + threadIdx.x) >> 5;
    const int nwarps = (gridDim.x * blockDim.x) >> 5;

    for (int base = warp_g * 4; base < m; base += nwarps * 4) {
        const int p   = base + group;
        const bool ok = (p < m);
        const unsigned long long v = g_ovf[ok ? p : 0];

        const int idx = (int)(v & 0xFFFFFu);
        const int ti  = (int)((v >> 20) & 0xFFFFFu);
        const int ci  = (int)(v >> 40);

        const float4* __restrict__ tv =
            reinterpret_cast<const float4*>(tgt_w + ((size_t)ti << D_SHIFT));
        const float4* __restrict__ cv =
            reinterpret_cast<const float4*>(cxt_w + ((size_t)ci << D_SHIFT));

        float sv = 0.f;
        #pragma unroll
        for (int k = 0; k < 4; k++) {
            const float4 a = __ldg(&cv[j + 8 * k]);
            const float4 b = __ldg(&tv[j + 8 * k]);
            sv = fmaf(a.x, b.x, sv); sv = fmaf(a.y, b.y, sv);
            sv = fmaf(a.z, b.z, sv); sv = fmaf(a.w, b.w, sv);
        }
        sv += __shfl_xor_sync(0xFFFFFFFFu, sv, 4);
        sv += __shfl_xor_sync(0xFFFFFFFFu, sv, 2);
        sv += __shfl_xor_sync(0xFFFFFFFFu, sv, 1);

        if (ok && j == 0)
            __stcs(&out[idx], sv);
    }
}

// ---------- fallback: proven direct kernel (R3 geometry, ~70us) ----------
__global__ void __launch_bounds__(256)
direct_kernel(const int* __restrict__ ctx_idx,
              const int* __restrict__ tgt_idx,
              const float* __restrict__ cxt_w,
              const float* __restrict__ tgt_w,
              float* __restrict__ out, int n)
{
    const int warp_id = (blockIdx.x * blockDim.x + threadIdx.x) >> 5;
    const int lane    = threadIdx.x & 31;
    const int group   = lane >> 3;
    const int j       = lane & 7;
    const int pair    = warp_id * 4 + group;
    if (pair >= n) return;

    const long long c = (long long)__ldg(&ctx_idx[pair]);
    const long long t = (long long)__ldg(&tgt_idx[pair]);
    const float4* __restrict__ cv = reinterpret_cast<const float4*>(cxt_w + c * 128);
    const float4* __restrict__ tv = reinterpret_cast<const float4*>(tgt_w + t * 128);

    float s = 0.f;
    #pragma unroll
    for (int k = 0; k < 4; k++) {
        const float4 a = __ldg(&cv[j + 8 * k]);
        const float4 b = __ldg(&tv[j + 8 * k]);
        s = fmaf(a.x, b.x, s); s = fmaf(a.y, b.y, s);
        s = fmaf(a.z, b.z, s); s = fmaf(a.w, b.w, s);
    }
    s += __shfl_xor_sync(0xFFFFFFFFu, s, 4);
    s += __shfl_xor_sync(0xFFFFFFFFu, s, 2);
    s += __shfl_xor_sync(0xFFFFFFFFu, s, 1);

    if (j == 0)
        __stcs(&out[pair], s);
}

extern "C" void kernel_launch(void* const* d_in, const int* in_sizes, int n_in,
                              void* d_out, int out_size)
{
    const int*   ctx_idx = (const int*)d_in[0];
    const int*   tgt_idx = (const int*)d_in[1];
    const float* cxt_w   = (const float*)d_in[2];
    const float* tgt_w   = (const float*)d_in[3];
    float*       out     = (float*)d_out;

    const int n = in_sizes[0];                 // 1,000,000 pairs
    const int V = in_sizes[2] >> D_SHIFT;      // 100,000 rows

    const bool shapes_ok = (n > 0) && (n <= NMAX_) &&
                           ((in_sizes[2] & 127) == 0) &&
                           (V <= (BMAX << B_SHIFT)) && (V <= (1 << 20));

    if (shapes_ok) {
        void* cp = nullptr; void* op = nullptr;
        cudaGetSymbolAddress(&cp, g_cursor);
        cudaGetSymbolAddress(&op, g_ovcnt);
        cudaMemsetAsync(cp, 0, BMAX * SUBS * sizeof(int));
        cudaMemsetAsync(op, 0, sizeof(int));

        const int sthreads = 256;
        const int spairs   = sthreads * 4;
        scatter_kernel<<<(n + spairs - 1) / spairs, sthreads>>>(ctx_idx, tgt_idx, n);

        const int NB = (V + ROWS_PB - 1) >> B_SHIFT;
        dot_kernel<<<NB, 512>>>(cxt_w, tgt_w, out, V);
        ovf_kernel<<<64, 256>>>(cxt_w, tgt_w, out);
    } else {
        const int threads = 256;
        const int pairs_per_block = (threads / 32) * 4;
        const int blocks = (n + pairs_per_block - 1) / pairs_per_block;
        direct_kernel<<<blocks, threads>>>(ctx_idx, tgt_idx, cxt_w, tgt_w, out, n);
    }
}

// round 14
// speedup vs baseline: 1.1673x; 1.0647x over previous
#include <cuda_runtime.h>
#include <stdint.h>

// SkipGramNS: out[i] = dot(cxt_weight[ctx_idx[i]], tgt_weight[tgt_idx[i]])
// N=1e6, D=128, V=1e5.
//
// R14: bucket pairs by EXACT context row (V buckets, ~10 pairs each).
// Dot: one warp per row; C row lives in REGISTERS (float4/lane, loaded once,
// ~4 wf amortized over ~10 pairs). Per pair: one warp-wide T row load
// (4 L1tex wavefronts) + reduce. ~5.5 wf/pair vs 8 for the direct kernel.
// Scatter: per-row cursors -> contention ~10/address (R13 proved atomics
// serialization was the scatter binder at 320/address).

#define D_SHIFT   7              // D = 128
#define ROWMAX    131072         // supports V <= 131072
#define SLOTS     40             // Poisson(10): P(>40) ~ 1e-13 per row
#define NMAX_     (1 << 20)      // supports n <= 1,048,576

__device__ int                g_cursor[ROWMAX];
__device__ int                g_ovcnt;
__device__ unsigned long long g_scratch[(size_t)ROWMAX * SLOTS];  // ~42MB
__device__ unsigned long long g_ovf[NMAX_];                       // 8MB

__device__ __forceinline__ unsigned long long pack_pair(int c, int t, int i) {
    return (unsigned long long)i |                 // 20 bits
           ((unsigned long long)t << 20) |         // 17 bits
           ((unsigned long long)c << 40);          // 17 bits
}

// ---------- K1: scatter, 4 pairs/thread, branchless atomic batch ----------
__global__ void __launch_bounds__(256)
scatter_kernel(const int* __restrict__ ci, const int* __restrict__ ti, int n)
{
    const int gtid = blockIdx.x * blockDim.x + threadIdx.x;
    const int i4   = gtid * 4;
    if (i4 >= n) return;

    if (i4 + 3 < n) {
        const int4 c = __ldg(reinterpret_cast<const int4*>(ci + i4));
        const int4 t = __ldg(reinterpret_cast<const int4*>(ti + i4));

        const int s0 = atomicAdd(&g_cursor[c.x], 1);
        const int s1 = atomicAdd(&g_cursor[c.y], 1);
        const int s2 = atomicAdd(&g_cursor[c.z], 1);
        const int s3 = atomicAdd(&g_cursor[c.w], 1);

        const unsigned long long v0 = pack_pair(c.x, t.x, i4);
        const unsigned long long v1 = pack_pair(c.y, t.y, i4 + 1);
        const unsigned long long v2 = pack_pair(c.z, t.z, i4 + 2);
        const unsigned long long v3 = pack_pair(c.w, t.w, i4 + 3);

        if (s0 < SLOTS) g_scratch[(size_t)c.x * SLOTS + s0] = v0;
        else            g_ovf[atomicAdd(&g_ovcnt, 1)] = v0;
        if (s1 < SLOTS) g_scratch[(size_t)c.y * SLOTS + s1] = v1;
        else            g_ovf[atomicAdd(&g_ovcnt, 1)] = v1;
        if (s2 < SLOTS) g_scratch[(size_t)c.z * SLOTS + s2] = v2;
        else            g_ovf[atomicAdd(&g_ovcnt, 1)] = v2;
        if (s3 < SLOTS) g_scratch[(size_t)c.w * SLOTS + s3] = v3;
        else            g_ovf[atomicAdd(&g_ovcnt, 1)] = v3;
    } else {
        for (int i = i4; i < n; i++) {
            const int c = __ldg(&ci[i]);
            const int t = __ldg(&ti[i]);
            const int s = atomicAdd(&g_cursor[c], 1);
            const unsigned long long v = pack_pair(c, t, i);
            if (s < SLOTS) g_scratch[(size_t)c * SLOTS + s] = v;
            else           g_ovf[atomicAdd(&g_ovcnt, 1)] = v;
        }
    }
}

// ---------- K2: dot, ONE WARP PER CONTEXT ROW, C row in registers ----------
__global__ void __launch_bounds__(256)
dot_kernel(const float* __restrict__ cxt_w,
           const float* __restrict__ tgt_w,
           float* __restrict__ out, int V)
{
    const int warp_g = (blockIdx.x * blockDim.x + threadIdx.x) >> 5;
    if (warp_g >= V) return;                      // warp-uniform
    const int lane = threadIdx.x & 31;

    const int cnt = min(__ldg(&g_cursor[warp_g]), SLOTS);
    if (cnt == 0) return;                         // warp-uniform

    // C row: one float4 per lane, held in registers for all ~10 pairs
    const float4 a = __ldg(reinterpret_cast<const float4*>(
                               cxt_w + ((size_t)warp_g << D_SHIFT)) + lane);

    const unsigned long long* __restrict__ seg =
        g_scratch + (size_t)warp_g * SLOTS;

    for (int base = 0; base < cnt; base += 32) {
        const int m = min(32, cnt - base);
        unsigned long long v = 0;
        if (base + lane < cnt) v = __ldg(&seg[base + lane]);
        const int myti  = (int)((v >> 20) & 0x1FFFFu);
        const int myidx = (int)(v & 0xFFFFFu);

        for (int k = 0; k < m; k++) {
            const int ti  = __shfl_sync(0xFFFFFFFFu, myti,  k);
            const int idx = __shfl_sync(0xFFFFFFFFu, myidx, k);

            const float4 b = __ldg(reinterpret_cast<const float4*>(
                                       tgt_w + ((size_t)ti << D_SHIFT)) + lane);

            float s = a.x * b.x;
            s = fmaf(a.y, b.y, s);
            s = fmaf(a.z, b.z, s);
            s = fmaf(a.w, b.w, s);

            #pragma unroll
            for (int off = 16; off > 0; off >>= 1)
                s += __shfl_xor_sync(0xFFFFFFFFu, s, off);

            if (lane == 0)
                __stcs(&out[idx], s);
        }
    }
}

// ---------- K3: overflow sweep (normally 0 pairs) ----------
__global__ void __launch_bounds__(256)
ovf_kernel(const float* __restrict__ cxt_w,
           const float* __restrict__ tgt_w,
           float* __restrict__ out)
{
    const int m = g_ovcnt;
    if (m == 0) return;

    const int lane   = threadIdx.x & 31;
    const int group  = lane >> 3;
    const int j      = lane & 7;
    const int warp_g = (blockIdx.x * blockDim.x + threadIdx.x) >> 5;
    const int nwarps = (gridDim.x * blockDim.x) >> 5;

    for (int base = warp_g * 4; base < m; base += nwarps * 4) {
        const int p   = base + group;
        const bool ok = (p < m);
        const unsigned long long v = g_ovf[ok ? p : 0];

        const int idx = (int)(v & 0xFFFFFu);
        const int ti  = (int)((v >> 20) & 0x1FFFFu);
        const int ci  = (int)((v >> 40) & 0x1FFFFu);

        const float4* __restrict__ tv =
            reinterpret_cast<const float4*>(tgt_w + ((size_t)ti << D_SHIFT));
        const float4* __restrict__ cv =
            reinterpret_cast<const float4*>(cxt_w + ((size_t)ci << D_SHIFT));

        float sv = 0.f;
        #pragma unroll
        for (int k = 0; k < 4; k++) {
            const float4 a = __ldg(&cv[j + 8 * k]);
            const float4 b = __ldg(&tv[j + 8 * k]);
            sv = fmaf(a.x, b.x, sv); sv = fmaf(a.y, b.y, sv);
            sv = fmaf(a.z, b.z, sv); sv = fmaf(a.w, b.w, sv);
        }
        sv += __shfl_xor_sync(0xFFFFFFFFu, sv, 4);
        sv += __shfl_xor_sync(0xFFFFFFFFu, sv, 2);
        sv += __shfl_xor_sync(0xFFFFFFFFu, sv, 1);

        if (ok && j == 0)
            __stcs(&out[idx], sv);
    }
}

// ---------- fallback: proven direct kernel (R3 geometry, ~70us) ----------
__global__ void __launch_bounds__(256)
direct_kernel(const int* __restrict__ ctx_idx,
              const int* __restrict__ tgt_idx,
              const float* __restrict__ cxt_w,
              const float* __restrict__ tgt_w,
              float* __restrict__ out, int n)
{
    const int warp_id = (blockIdx.x * blockDim.x + threadIdx.x) >> 5;
    const int lane    = threadIdx.x & 31;
    const int group   = lane >> 3;
    const int j       = lane & 7;
    const int pair    = warp_id * 4 + group;
    if (pair >= n) return;

    const long long c = (long long)__ldg(&ctx_idx[pair]);
    const long long t = (long long)__ldg(&tgt_idx[pair]);
    const float4* __restrict__ cv = reinterpret_cast<const float4*>(cxt_w + c * 128);
    const float4* __restrict__ tv = reinterpret_cast<const float4*>(tgt_w + t * 128);

    float s = 0.f;
    #pragma unroll
    for (int k = 0; k < 4; k++) {
        const float4 a = __ldg(&cv[j + 8 * k]);
        const float4 b = __ldg(&tv[j + 8 * k]);
        s = fmaf(a.x, b.x, s); s = fmaf(a.y, b.y, s);
        s = fmaf(a.z, b.z, s); s = fmaf(a.w, b.w, s);
    }
    s += __shfl_xor_sync(0xFFFFFFFFu, s, 4);
    s += __shfl_xor_sync(0xFFFFFFFFu, s, 2);
    s += __shfl_xor_sync(0xFFFFFFFFu, s, 1);

    if (j == 0)
        __stcs(&out[pair], s);
}

extern "C" void kernel_launch(void* const* d_in, const int* in_sizes, int n_in,
                              void* d_out, int out_size)
{
    const int*   ctx_idx = (const int*)d_in[0];
    const int*   tgt_idx = (const int*)d_in[1];
    const float* cxt_w   = (const float*)d_in[2];
    const float* tgt_w   = (const float*)d_in[3];
    float*       out     = (float*)d_out;

    const int n = in_sizes[0];                 // 1,000,000 pairs
    const int V = in_sizes[2] >> D_SHIFT;      // 100,000 rows

    const bool shapes_ok = (n > 0) && (n <= NMAX_) &&
                           ((in_sizes[2] & 127) == 0) &&
                           (V <= ROWMAX) &&
                           ((in_sizes[3] >> D_SHIFT) <= ROWMAX);

    if (shapes_ok) {
        void* cp = nullptr; void* op = nullptr;
        cudaGetSymbolAddress(&cp, g_cursor);
        cudaGetSymbolAddress(&op, g_ovcnt);
        cudaMemsetAsync(cp, 0, (size_t)V * sizeof(int));
        cudaMemsetAsync(op, 0, sizeof(int));

        const int sthreads = 256;
        const int spairs   = sthreads * 4;
        scatter_kernel<<<(n + spairs - 1) / spairs, sthreads>>>(ctx_idx, tgt_idx, n);

        const int warps_per_blk = 256 / 32;    // 8 rows per CTA
        dot_kernel<<<(V + warps_per_blk - 1) / warps_per_blk, 256>>>(
            cxt_w, tgt_w, out, V);
        ovf_kernel<<<64, 256>>>(cxt_w, tgt_w, out);
    } else {
        const int threads = 256;
        const int pairs_per_block = (threads / 32) * 4;
        const int blocks = (n + pairs_per_block - 1) / pairs_per_block;
        direct_kernel<<<blocks, threads>>>(ctx_idx, tgt_idx, cxt_w, tgt_w, out, n);
    }
}